// round 2
// baseline (speedup 1.0000x reference)
#include <cuda_runtime.h>
#include <cstdint>

// ---------------- problem constants ----------------
#define BATCH 4
#define CH    256
#define HW    64
#define NPIX  (HW*HW)          // 4096 pixels per image
#define OHW   62               // valid patch positions per dim
#define NP    (OHW*OHW)        // 3844 patches
#define EPSN  1e-12f

// ---------------- scratch (device globals; no allocs) ----------------
__device__ float g_Pn[BATCH*CH*NPIX];          // normalized pred   (c-major rows, pixel contiguous)
__device__ float g_Tn[BATCH*CH*NPIX];          // normalized target
__device__ float g_pnorm[BATCH*NPIX];
__device__ float g_psq  [BATCH*NPIX];
__device__ float g_tnorm[BATCH*NPIX];
__device__ float g_tsq  [BATCH*NPIX];
__device__ float g_D[(size_t)BATCH*NPIX*NPIX]; // 268 MB correlation matrices
__device__ int   g_match[BATCH*NP];
__device__ float g_partial[BATCH*OHW];         // 248 block partials for loss

// ---------------- K1: per-pixel L2 normalize over channels ----------------
// block = 256 threads = 32 pixels x 8 channel-slices; grid = 16384/32 = 512
__global__ void normalize_kernel(const float* __restrict__ x, int which)
{
    __shared__ float red[8][32];
    __shared__ float rs[32];
    float* __restrict__ xn  = which ? g_Tn    : g_Pn;
    float* __restrict__ nrm = which ? g_tnorm : g_pnorm;
    float* __restrict__ sq  = which ? g_tsq   : g_psq;

    int tx = threadIdx.x & 31, ty = threadIdx.x >> 5;
    int g0 = blockIdx.x * 32;            // first global pixel id (b*4096+pix)
    int b  = g0 >> 12;
    int pix = (g0 & 4095) + tx;
    size_t base = (size_t)b * (CH*NPIX) + pix;

    float s = 0.f;
    #pragma unroll
    for (int k = 0; k < 32; k++) {
        float v = x[base + (size_t)(ty*32 + k) * NPIX];
        s += v * v;
    }
    red[ty][tx] = s;
    __syncthreads();
    if (ty == 0) {
        float tot = 0.f;
        #pragma unroll
        for (int j = 0; j < 8; j++) tot += red[j][tx];
        float n = sqrtf(tot);
        nrm[g0 + tx] = n;
        sq [g0 + tx] = tot;
        rs[tx] = 1.f / fmaxf(n, EPSN);
    }
    __syncthreads();
    float r = rs[tx];
    #pragma unroll
    for (int k = 0; k < 32; k++) {
        size_t o = base + (size_t)(ty*32 + k) * NPIX;
        xn[o] = x[o] * r;
    }
}

// ---------------- K2: D[b] = Pn[b]^T * Tn[b]  (4096x4096, K=256), fp32 ----------------
// 128x128 block tile, BK=16, 256 threads, 8x8 per-thread micro-tile
#define BM 128
#define BN 128
#define BK 16
__global__ void __launch_bounds__(256) gemm_tn_kernel()
{
    int b  = blockIdx.z;
    const float* __restrict__ A = g_Pn + (size_t)b * (CH*NPIX);
    const float* __restrict__ B = g_Tn + (size_t)b * (CH*NPIX);
    float* __restrict__ Db      = g_D  + (size_t)b * NPIX * NPIX;

    int u0 = blockIdx.y * BM;
    int v0 = blockIdx.x * BN;

    __shared__ float As[BK][BM];
    __shared__ float Bs[BK][BN];

    int tid = threadIdx.x;
    int tx = tid & 15, ty = tid >> 4;

    float acc[8][8];
    #pragma unroll
    for (int i = 0; i < 8; i++)
        #pragma unroll
        for (int j = 0; j < 8; j++) acc[i][j] = 0.f;

    for (int kt = 0; kt < CH; kt += BK) {
        // cooperative load: 16x128 floats per tile = 512 float4; 2 per thread
        #pragma unroll
        for (int i = 0; i < 2; i++) {
            int f  = tid + i * 256;
            int r  = f >> 5;
            int c4 = (f & 31) << 2;
            size_t go = (size_t)(kt + r) * NPIX;
            *(float4*)&As[r][c4] = *(const float4*)(A + go + u0 + c4);
            *(float4*)&Bs[r][c4] = *(const float4*)(B + go + v0 + c4);
        }
        __syncthreads();
        #pragma unroll
        for (int k = 0; k < BK; k++) {
            float ar[8], br[8];
            #pragma unroll
            for (int i = 0; i < 4; i++) { ((float4*)ar)[0] = *(float4*)&As[k][ty*8];
                                          ((float4*)ar)[1] = *(float4*)&As[k][ty*8+4];
                                          break; }
            #pragma unroll
            for (int j = 0; j < 4; j++) { ((float4*)br)[0] = *(float4*)&Bs[k][tx*8];
                                          ((float4*)br)[1] = *(float4*)&Bs[k][tx*8+4];
                                          break; }
            #pragma unroll
            for (int i = 0; i < 8; i++)
                #pragma unroll
                for (int j = 0; j < 8; j++)
                    acc[i][j] += ar[i] * br[j];
        }
        __syncthreads();
    }

    #pragma unroll
    for (int i = 0; i < 8; i++) {
        size_t row = (size_t)(u0 + ty*8 + i) * NPIX + v0 + tx*8;
        *(float4*)(Db + row)     = *(float4*)&acc[i][0];
        *(float4*)(Db + row + 4) = *(float4*)&acc[i][4];
    }
}

// ---------------- K3: fused 9-diagonal score + row argmax ----------------
// block per (b,q): 15376 blocks x 128 threads
__constant__ int c_doff[9] = {0,1,2,64,65,66,128,129,130};

__global__ void __launch_bounds__(128) argmax_kernel()
{
    int bq = blockIdx.x;
    int b = bq / NP;
    int q = bq - b * NP;
    int qr = q / OHW, qc = q - qr * OHW;
    int qpix = qr * HW + qc;

    const float* __restrict__ Dq = g_D + (size_t)b * NPIX * NPIX;
    const float* rows[9];
    #pragma unroll
    for (int e = 0; e < 9; e++)
        rows[e] = Dq + (size_t)(qpix + c_doff[e]) * NPIX + c_doff[e];

    int t = threadIdx.x;
    float best = -3.4e38f;
    int bestp = 0x7fffffff;

    for (int p = t; p < NP; p += 128) {
        int pr = p / OHW, pc = p - pr * OHW;
        int ppix = pr * HW + pc;
        float s = 0.f;
        #pragma unroll
        for (int e = 0; e < 9; e++) s += rows[e][ppix];
        if (s > best) { best = s; bestp = p; }   // ascending p -> first max kept
    }

    __shared__ float sb[128];
    __shared__ int   sp[128];
    sb[t] = best; sp[t] = bestp;
    __syncthreads();
    #pragma unroll
    for (int s = 64; s > 0; s >>= 1) {
        if (t < s) {
            bool take = (sb[t+s] > sb[t]) || (sb[t+s] == sb[t] && sp[t+s] < sp[t]);
            if (take) { sb[t] = sb[t+s]; sp[t] = sp[t+s]; }
        }
        __syncthreads();
    }
    if (t == 0) g_match[bq] = sp[0];
}

// ---------------- K4: closed-form MSE per query ----------------
// ||pp - t||^2 = sum_d psq[u] + tsq[v] - 2*pnorm[u]*tnorm[v]*D[u,v]
// grid = 4*62 blocks (b, qr), 64 threads (qc)
__global__ void __launch_bounds__(64) loss_kernel()
{
    int b  = blockIdx.x / OHW;
    int qr = blockIdx.x - b * OHW;
    int qc = threadIdx.x;
    float val = 0.f;
    if (qc < OHW) {
        int q = qr * OHW + qc;
        int m = g_match[b * NP + q];
        int mr = m / OHW, mc = m - mr * OHW;
        int qpix = qr * HW + qc;
        int mpix = mr * HW + mc;
        const float* __restrict__ Dq = g_D + (size_t)b * NPIX * NPIX;
        int nb = b * NPIX;
        #pragma unroll
        for (int e = 0; e < 9; e++) {
            int d = c_doff[e];
            int u = qpix + d, v = mpix + d;
            float cross = g_pnorm[nb + u] * g_tnorm[nb + v] * Dq[(size_t)u * NPIX + v];
            val += g_psq[nb + u] + g_tsq[nb + v] - 2.f * cross;
        }
    }
    __shared__ float red[64];
    red[threadIdx.x] = val;
    __syncthreads();
    #pragma unroll
    for (int s = 32; s > 0; s >>= 1) {
        if (threadIdx.x < s) red[threadIdx.x] += red[threadIdx.x + s];
        __syncthreads();
    }
    if (threadIdx.x == 0) g_partial[blockIdx.x] = red[0];
}

// ---------------- K5: final reduce -> scalar mean ----------------
__global__ void __launch_bounds__(256) finalize_kernel(float* __restrict__ out)
{
    int t = threadIdx.x;
    float v = (t < BATCH * OHW) ? g_partial[t] : 0.f;
    __shared__ float red[256];
    red[t] = v;
    __syncthreads();
    #pragma unroll
    for (int s = 128; s > 0; s >>= 1) {
        if (t < s) red[t] += red[t + s];
        __syncthreads();
    }
    if (t == 0) out[0] = red[0] * (1.f / 35426304.f);  // 4*3844*256*9
}

// ---------------- launch ----------------
extern "C" void kernel_launch(void* const* d_in, const int* in_sizes, int n_in,
                              void* d_out, int out_size)
{
    const float* pred = (const float*)d_in[0];
    const float* targ = (const float*)d_in[1];
    float* out = (float*)d_out;

    normalize_kernel<<<512, 256>>>(pred, 0);
    normalize_kernel<<<512, 256>>>(targ, 1);

    dim3 ggrid(NPIX / BN, NPIX / BM, BATCH);   // 32 x 32 x 4
    gemm_tn_kernel<<<ggrid, 256>>>();

    argmax_kernel<<<BATCH * NP, 128>>>();

    loss_kernel<<<BATCH * OHW, 64>>>();
    finalize_kernel<<<1, 256>>>(out);
}

// round 8
// speedup vs baseline: 2.0330x; 2.0330x over previous
#include <cuda_runtime.h>
#include <cuda_bf16.h>
#include <cstdint>

// ---------------- problem constants ----------------
#define BATCH 4
#define CH    256
#define HW    64
#define NPIX  (HW*HW)          // 4096
#define OHW   62
#define NP    (OHW*OHW)        // 3844
#define KCAT  768              // [ah|ah|al] x [bh|bl|bh]
#define EPSN  1e-12f

// ---------------- scratch ----------------
__device__ __nv_bfloat16 g_Acat[(size_t)BATCH*NPIX*KCAT];  // pred:   [h|h|l] per pixel row
__device__ __nv_bfloat16 g_Bcat[(size_t)BATCH*NPIX*KCAT];  // target: [h|l|h]
__device__ float g_pnorm[BATCH*NPIX];
__device__ float g_psq  [BATCH*NPIX];
__device__ float g_tnorm[BATCH*NPIX];
__device__ float g_tsq  [BATCH*NPIX];
__device__ float g_D[(size_t)BATCH*NPIX*NPIX];             // 268 MB
__device__ int   g_match[BATCH*NP];
__device__ float g_partial[BATCH*OHW];

// ---------------- helpers ----------------
__device__ __forceinline__ uint32_t s2u(const void* p) {
    uint32_t a;
    asm("{ .reg .u64 t; cvta.to.shared.u64 t, %1; cvt.u32.u64 %0, t; }" : "=r"(a) : "l"(p));
    return a;
}

#define LDMATRIX_X4(r, addr) \
    asm volatile("ldmatrix.sync.aligned.m8n8.x4.shared.b16 {%0,%1,%2,%3}, [%4];" \
                 : "=r"((r)[0]), "=r"((r)[1]), "=r"((r)[2]), "=r"((r)[3]) : "r"(addr))

#define MMA16816(d, a, b0, b1) \
    asm volatile("mma.sync.aligned.m16n8k16.row.col.f32.bf16.bf16.f32 " \
                 "{%0,%1,%2,%3}, {%4,%5,%6,%7}, {%8,%9}, {%0,%1,%2,%3};" \
                 : "+f"((d)[0]), "+f"((d)[1]), "+f"((d)[2]), "+f"((d)[3]) \
                 : "r"((a)[0]), "r"((a)[1]), "r"((a)[2]), "r"((a)[3]), "r"(b0), "r"(b1))

// ---------------- K1: normalize + bf16-split + pack K-major cats ----------------
// block = 256 thr = 32 px x 8 chan-groups
__global__ void __launch_bounds__(256) normalize_kernel(const float* __restrict__ x, int which)
{
    __shared__ float red[8][32];
    __shared__ float rs[32];
    __shared__ __nv_bfloat16 stage[32][514];   // [h(256) | l(256) | pad2]

    float* __restrict__ nrm = which ? g_tnorm : g_pnorm;
    float* __restrict__ sq  = which ? g_tsq   : g_psq;

    int tx = threadIdx.x & 31, ty = threadIdx.x >> 5;
    int g0 = blockIdx.x * 32;
    int b  = g0 >> 12;
    int pix = (g0 & 4095) + tx;
    size_t base = (size_t)b * (CH*NPIX) + pix;

    float s = 0.f;
    #pragma unroll
    for (int k = 0; k < 32; k++) {
        float v = x[base + (size_t)(ty*32 + k) * NPIX];
        s += v * v;
    }
    red[ty][tx] = s;
    __syncthreads();
    if (ty == 0) {
        float tot = 0.f;
        #pragma unroll
        for (int j = 0; j < 8; j++) tot += red[j][tx];
        float n = sqrtf(tot);
        nrm[g0 + tx] = n;
        sq [g0 + tx] = tot;
        rs[tx] = 1.f / fmaxf(n, EPSN);
    }
    __syncthreads();
    float r = rs[tx];
    #pragma unroll
    for (int k = 0; k < 32; k++) {
        float f = x[base + (size_t)(ty*32 + k) * NPIX] * r;
        __nv_bfloat16 h = __float2bfloat16(f);
        __nv_bfloat16 l = __float2bfloat16(f - __bfloat162float(h));
        int c = ty*32 + k;
        stage[tx][c]       = h;
        stage[tx][256 + c] = l;
    }
    __syncthreads();

    // pred (which=0): regions [h,h,l]; targ: [h,l,h]
    int sel1 = which ? 1 : 0;
    int sel2 = which ? 0 : 1;
    uint32_t* __restrict__ dst = (uint32_t*)(which ? g_Bcat : g_Acat);
    const uint32_t* __restrict__ src = (const uint32_t*)&stage[0][0];  // pitch 257 u32
    #pragma unroll
    for (int i = 0; i < 48; i++) {
        int f = threadIdx.x + i * 256;      // 0..12287
        int row = f / 384;
        int rem = f - row * 384;
        int region = rem >> 7;
        int j = rem & 127;
        int sel = (region == 0) ? 0 : ((region == 1) ? sel1 : sel2);
        uint32_t val = src[row * 257 + sel * 128 + j];
        dst[(size_t)(g0 + row) * 384 + region * 128 + j] = val;
    }
}

// ---------------- K2: HMMA bf16 GEMM  D = Acat * Bcat^T  (4096x4096, K=768) ----------------
#define TM 128
#define TN 128
#define BKC 64                // bf16 per chunk = 128 bytes/row (SW128)
#define NCHUNK (KCAT/BKC)     // 12
#define STAGE_BYTES 32768     // A 16K + B 16K
#define GEMM_SMEM (2*STAGE_BYTES)

static __device__ __forceinline__ void load_chunk(
    const __nv_bfloat16* __restrict__ A, const __nv_bfloat16* __restrict__ Bm,
    int u0, int v0, int c, uint32_t sdst, int tid)
{
    #pragma unroll
    for (int i = 0; i < 8; i++) {
        int f = tid + i * 256;            // 0..2047 uint4
        int tile = f >> 10;               // 0=A, 1=B
        int wi = f & 1023;
        int row = wi >> 3, c16 = wi & 7;
        uint32_t off = (uint32_t)((row << 7) | (c16 << 4));
        uint32_t sw = off ^ ((off >> 3) & 0x70);
        const __nv_bfloat16* src =
            (tile ? Bm : A) + (size_t)((tile ? v0 : u0) + row) * KCAT + c * BKC + c16 * 8;
        uint32_t daddr = sdst + tile * 16384 + sw;
        asm volatile("cp.async.cg.shared.global [%0], [%1], 16;" :: "r"(daddr), "l"(src));
    }
    asm volatile("cp.async.commit_group;");
}

__global__ void __launch_bounds__(256, 2) gemm_kernel()
{
    extern __shared__ char smem[];
    uint32_t sb = s2u(smem);
    int tid = threadIdx.x, wid = tid >> 5, lane = tid & 31;
    int b = blockIdx.z;
    int u0 = blockIdx.y * TM, v0 = blockIdx.x * TN;
    const __nv_bfloat16* A  = g_Acat + (size_t)b * NPIX * KCAT;
    const __nv_bfloat16* Bm = g_Bcat + (size_t)b * NPIX * KCAT;

    int wm = (wid & 1) * 64;   // 2 warps in M
    int wn = (wid >> 1) * 32;  // 4 warps in N

    float acc[4][4][4];
    #pragma unroll
    for (int mt = 0; mt < 4; mt++)
        #pragma unroll
        for (int nt = 0; nt < 4; nt++)
            #pragma unroll
            for (int e = 0; e < 4; e++) acc[mt][nt][e] = 0.f;

    // UNSWIZZLED ldmatrix base addresses + per-lane swizzle row masks.
    // Per k-step: addr = (base + ks*32) ^ mask. Column part (<=112) never
    // carries into the row bits, so applying the XOR after the add is exact.
    uint32_t a_base[4], a_msk[4], b_base[2], b_msk[2];
    #pragma unroll
    for (int mt = 0; mt < 4; mt++) {
        int row = wm + mt*16 + (lane & 15);
        a_base[mt] = (uint32_t)(row * 128 + ((lane >> 4) * 16));
        a_msk[mt]  = (uint32_t)((row & 7) << 4);
    }
    #pragma unroll
    for (int g = 0; g < 2; g++) {
        int nt    = g*2 + ((lane >> 4) & 1);   // lanes 16-31 -> second n-tile
        int khalf = (lane >> 3) & 1;           // k-low / k-high 8
        int row   = wn + nt*8 + (lane & 7);
        b_base[g] = (uint32_t)(16384 + row * 128 + khalf * 16);
        b_msk[g]  = (uint32_t)((row & 7) << 4);
    }

    load_chunk(A, Bm, u0, v0, 0, sb, tid);

    #pragma unroll 1
    for (int c = 0; c < NCHUNK; c++) {
        int s = c & 1;
        if (c + 1 < NCHUNK) {
            load_chunk(A, Bm, u0, v0, c + 1, sb + (s ^ 1) * STAGE_BYTES, tid);
            asm volatile("cp.async.wait_group 1;");
        } else {
            asm volatile("cp.async.wait_group 0;");
        }
        __syncthreads();

        uint32_t cbase = sb + s * STAGE_BYTES;
        #pragma unroll
        for (int ks = 0; ks < 4; ks++) {
            uint32_t a_frag[4][4], b_frag[2][4];
            #pragma unroll
            for (int mt = 0; mt < 4; mt++)
                LDMATRIX_X4(a_frag[mt], cbase + ((a_base[mt] + ks*32) ^ a_msk[mt]));
            #pragma unroll
            for (int g = 0; g < 2; g++)
                LDMATRIX_X4(b_frag[g], cbase + ((b_base[g] + ks*32) ^ b_msk[g]));
            #pragma unroll
            for (int mt = 0; mt < 4; mt++)
                #pragma unroll
                for (int nt = 0; nt < 4; nt++)
                    MMA16816(acc[mt][nt], a_frag[mt],
                             b_frag[nt >> 1][(nt & 1) * 2],
                             b_frag[nt >> 1][(nt & 1) * 2 + 1]);
        }
        __syncthreads();   // protect buffer s before next prefetch overwrites it
    }

    // epilogue: direct fragment stores; each quad writes a contiguous 32B segment
    float* __restrict__ Db = g_D + (size_t)b * NPIX * NPIX;
    int qrow = lane >> 2, qcol = (lane & 3) * 2;
    #pragma unroll
    for (int mt = 0; mt < 4; mt++) {
        #pragma unroll
        for (int nt = 0; nt < 4; nt++) {
            int r0  = u0 + wm + mt*16 + qrow;
            int col = v0 + wn + nt*8 + qcol;
            *(float2*)&Db[(size_t)r0       * NPIX + col] = make_float2(acc[mt][nt][0], acc[mt][nt][1]);
            *(float2*)&Db[(size_t)(r0 + 8) * NPIX + col] = make_float2(acc[mt][nt][2], acc[mt][nt][3]);
        }
    }
}

// ---------------- K3: 9-diagonal score + argmax ----------------
__constant__ int c_doff[9] = {0,1,2,64,65,66,128,129,130};

__global__ void __launch_bounds__(128) argmax_kernel()
{
    int bq = blockIdx.x;
    int b = bq / NP;
    int q = bq - b * NP;
    int qr = q / OHW, qc = q - qr * OHW;
    int qpix = qr * HW + qc;

    const float* __restrict__ Dq = g_D + (size_t)b * NPIX * NPIX;
    const float* rows[9];
    #pragma unroll
    for (int e = 0; e < 9; e++)
        rows[e] = Dq + (size_t)(qpix + c_doff[e]) * NPIX + c_doff[e];

    int t = threadIdx.x;
    float best = -3.4e38f;
    int bestp = 0x7fffffff;

    for (int p = t; p < NP; p += 128) {
        int pr = p / OHW, pc = p - pr * OHW;
        int ppix = pr * HW + pc;
        float s = 0.f;
        #pragma unroll
        for (int e = 0; e < 9; e++) s += rows[e][ppix];
        if (s > best) { best = s; bestp = p; }
    }

    __shared__ float sbv[128];
    __shared__ int   spv[128];
    sbv[t] = best; spv[t] = bestp;
    __syncthreads();
    #pragma unroll
    for (int s = 64; s > 0; s >>= 1) {
        if (t < s) {
            bool take = (sbv[t+s] > sbv[t]) || (sbv[t+s] == sbv[t] && spv[t+s] < spv[t]);
            if (take) { sbv[t] = sbv[t+s]; spv[t] = spv[t+s]; }
        }
        __syncthreads();
    }
    if (t == 0) g_match[bq] = spv[0];
}

// ---------------- K4: closed-form MSE ----------------
__global__ void __launch_bounds__(64) loss_kernel()
{
    int b  = blockIdx.x / OHW;
    int qr = blockIdx.x - b * OHW;
    int qc = threadIdx.x;
    float val = 0.f;
    if (qc < OHW) {
        int q = qr * OHW + qc;
        int m = g_match[b * NP + q];
        int mr = m / OHW, mc = m - mr * OHW;
        int qpix = qr * HW + qc;
        int mpix = mr * HW + mc;
        const float* __restrict__ Dq = g_D + (size_t)b * NPIX * NPIX;
        int nb = b * NPIX;
        #pragma unroll
        for (int e = 0; e < 9; e++) {
            int d = c_doff[e];
            int u = qpix + d, v = mpix + d;
            float cross = g_pnorm[nb + u] * g_tnorm[nb + v] * Dq[(size_t)u * NPIX + v];
            val += g_psq[nb + u] + g_tsq[nb + v] - 2.f * cross;
        }
    }
    __shared__ float red[64];
    red[threadIdx.x] = val;
    __syncthreads();
    #pragma unroll
    for (int s = 32; s > 0; s >>= 1) {
        if (threadIdx.x < s) red[threadIdx.x] += red[threadIdx.x + s];
        __syncthreads();
    }
    if (threadIdx.x == 0) g_partial[blockIdx.x] = red[0];
}

// ---------------- K5: final reduce ----------------
__global__ void __launch_bounds__(256) finalize_kernel(float* __restrict__ out)
{
    int t = threadIdx.x;
    float v = (t < BATCH * OHW) ? g_partial[t] : 0.f;
    __shared__ float red[256];
    red[t] = v;
    __syncthreads();
    #pragma unroll
    for (int s = 128; s > 0; s >>= 1) {
        if (t < s) red[t] += red[t + s];
        __syncthreads();
    }
    if (t == 0) out[0] = red[0] * (1.f / 35426304.f);
}

// ---------------- launch ----------------
extern "C" void kernel_launch(void* const* d_in, const int* in_sizes, int n_in,
                              void* d_out, int out_size)
{
    const float* pred = (const float*)d_in[0];
    const float* targ = (const float*)d_in[1];
    float* out = (float*)d_out;

    static int smem_set = 0;
    if (!smem_set) {
        cudaFuncSetAttribute(gemm_kernel, cudaFuncAttributeMaxDynamicSharedMemorySize, GEMM_SMEM);
        smem_set = 1;
    }

    normalize_kernel<<<512, 256>>>(pred, 0);
    normalize_kernel<<<512, 256>>>(targ, 1);

    dim3 ggrid(NPIX / TN, NPIX / TM, BATCH);   // 32 x 32 x 4
    gemm_kernel<<<ggrid, 256, GEMM_SMEM>>>();

    argmax_kernel<<<BATCH * NP, 128>>>();
    loss_kernel<<<BATCH * OHW, 64>>>();
    finalize_kernel<<<1, 256>>>(out);
}

// round 9
// speedup vs baseline: 2.2298x; 1.0968x over previous
#include <cuda_runtime.h>
#include <cuda_bf16.h>
#include <cstdint>

// ---------------- problem constants ----------------
#define BATCH 4
#define CH    256
#define HW    64
#define NPIX  (HW*HW)          // 4096
#define OHW   62
#define NP    (OHW*OHW)        // 3844
#define KCAT  768              // [ah|ah|al] x [bh|bl|bh]
#define EPSN  1e-12f

// ---------------- scratch ----------------
__device__ __nv_bfloat16 g_Acat[(size_t)BATCH*NPIX*KCAT];
__device__ __nv_bfloat16 g_Bcat[(size_t)BATCH*NPIX*KCAT];
__device__ float g_pnorm[BATCH*NPIX];
__device__ float g_psq  [BATCH*NPIX];
__device__ float g_tnorm[BATCH*NPIX];
__device__ float g_tsq  [BATCH*NPIX];
__device__ float g_D[(size_t)BATCH*NPIX*NPIX];             // 268 MB
__device__ unsigned long long g_pack[(size_t)BATCH*NP*OHW]; // per-(q,pr) partial argmax
__device__ int   g_match[BATCH*NP];
__device__ float g_partial[BATCH*OHW];

// ---------------- helpers ----------------
__device__ __forceinline__ uint32_t s2u(const void* p) {
    uint32_t a;
    asm("{ .reg .u64 t; cvta.to.shared.u64 t, %1; cvt.u32.u64 %0, t; }" : "=r"(a) : "l"(p));
    return a;
}
__device__ __forceinline__ unsigned long long umax64(unsigned long long a, unsigned long long b) {
    return a > b ? a : b;
}

#define LDMATRIX_X4(r, addr) \
    asm volatile("ldmatrix.sync.aligned.m8n8.x4.shared.b16 {%0,%1,%2,%3}, [%4];" \
                 : "=r"((r)[0]), "=r"((r)[1]), "=r"((r)[2]), "=r"((r)[3]) : "r"(addr))

#define MMA16816(d, a, b0, b1) \
    asm volatile("mma.sync.aligned.m16n8k16.row.col.f32.bf16.bf16.f32 " \
                 "{%0,%1,%2,%3}, {%4,%5,%6,%7}, {%8,%9}, {%0,%1,%2,%3};" \
                 : "+f"((d)[0]), "+f"((d)[1]), "+f"((d)[2]), "+f"((d)[3]) \
                 : "r"((a)[0]), "r"((a)[1]), "r"((a)[2]), "r"((a)[3]), "r"(b0), "r"(b1))

// ---------------- K1: normalize + bf16-split + pack K-major cats ----------------
__global__ void __launch_bounds__(256) normalize_kernel(const float* __restrict__ x, int which)
{
    __shared__ float red[8][32];
    __shared__ float rs[32];
    __shared__ __nv_bfloat16 stage[32][514];   // [h(256) | l(256) | pad2]

    float* __restrict__ nrm = which ? g_tnorm : g_pnorm;
    float* __restrict__ sq  = which ? g_tsq   : g_psq;

    int tx = threadIdx.x & 31, ty = threadIdx.x >> 5;
    int g0 = blockIdx.x * 32;
    int b  = g0 >> 12;
    int pix = (g0 & 4095) + tx;
    size_t base = (size_t)b * (CH*NPIX) + pix;

    float s = 0.f;
    #pragma unroll
    for (int k = 0; k < 32; k++) {
        float v = x[base + (size_t)(ty*32 + k) * NPIX];
        s += v * v;
    }
    red[ty][tx] = s;
    __syncthreads();
    if (ty == 0) {
        float tot = 0.f;
        #pragma unroll
        for (int j = 0; j < 8; j++) tot += red[j][tx];
        float n = sqrtf(tot);
        nrm[g0 + tx] = n;
        sq [g0 + tx] = tot;
        rs[tx] = 1.f / fmaxf(n, EPSN);
    }
    __syncthreads();
    float r = rs[tx];
    #pragma unroll
    for (int k = 0; k < 32; k++) {
        float f = x[base + (size_t)(ty*32 + k) * NPIX] * r;
        __nv_bfloat16 h = __float2bfloat16(f);
        __nv_bfloat16 l = __float2bfloat16(f - __bfloat162float(h));
        int c = ty*32 + k;
        stage[tx][c]       = h;
        stage[tx][256 + c] = l;
    }
    __syncthreads();

    int sel1 = which ? 1 : 0;
    int sel2 = which ? 0 : 1;
    uint32_t* __restrict__ dst = (uint32_t*)(which ? g_Bcat : g_Acat);
    const uint32_t* __restrict__ src = (const uint32_t*)&stage[0][0];  // pitch 257 u32
    #pragma unroll
    for (int i = 0; i < 48; i++) {
        int f = threadIdx.x + i * 256;
        int row = f / 384;
        int rem = f - row * 384;
        int region = rem >> 7;
        int j = rem & 127;
        int sel = (region == 0) ? 0 : ((region == 1) ? sel1 : sel2);
        uint32_t val = src[row * 257 + sel * 128 + j];
        dst[(size_t)(g0 + row) * 384 + region * 128 + j] = val;
    }
}

// ---------------- K2: HMMA bf16 GEMM  D = Acat * Bcat^T  (4096x4096, K=768) ----------------
#define TM 128
#define TN 128
#define BKC 64
#define NCHUNK (KCAT/BKC)     // 12
#define STAGE_BYTES 32768
#define GEMM_SMEM (2*STAGE_BYTES)

static __device__ __forceinline__ void load_chunk(
    const __nv_bfloat16* __restrict__ A, const __nv_bfloat16* __restrict__ Bm,
    int u0, int v0, int c, uint32_t sdst, int tid)
{
    #pragma unroll
    for (int i = 0; i < 8; i++) {
        int f = tid + i * 256;
        int tile = f >> 10;
        int wi = f & 1023;
        int row = wi >> 3, c16 = wi & 7;
        uint32_t off = (uint32_t)((row << 7) | (c16 << 4));
        uint32_t sw = off ^ ((off >> 3) & 0x70);
        const __nv_bfloat16* src =
            (tile ? Bm : A) + (size_t)((tile ? v0 : u0) + row) * KCAT + c * BKC + c16 * 8;
        uint32_t daddr = sdst + tile * 16384 + sw;
        asm volatile("cp.async.cg.shared.global [%0], [%1], 16;" :: "r"(daddr), "l"(src));
    }
    asm volatile("cp.async.commit_group;");
}

__global__ void __launch_bounds__(256, 2) gemm_kernel()
{
    extern __shared__ char smem[];
    uint32_t sb = s2u(smem);
    int tid = threadIdx.x, wid = tid >> 5, lane = tid & 31;
    int b = blockIdx.z;
    int u0 = blockIdx.y * TM, v0 = blockIdx.x * TN;
    const __nv_bfloat16* A  = g_Acat + (size_t)b * NPIX * KCAT;
    const __nv_bfloat16* Bm = g_Bcat + (size_t)b * NPIX * KCAT;

    int wm = (wid & 1) * 64;
    int wn = (wid >> 1) * 32;

    float acc[4][4][4];
    #pragma unroll
    for (int mt = 0; mt < 4; mt++)
        #pragma unroll
        for (int nt = 0; nt < 4; nt++)
            #pragma unroll
            for (int e = 0; e < 4; e++) acc[mt][nt][e] = 0.f;

    uint32_t a_base[4], a_msk[4], b_base[2], b_msk[2];
    #pragma unroll
    for (int mt = 0; mt < 4; mt++) {
        int row = wm + mt*16 + (lane & 15);
        a_base[mt] = (uint32_t)(row * 128 + ((lane >> 4) * 16));
        a_msk[mt]  = (uint32_t)((row & 7) << 4);
    }
    #pragma unroll
    for (int g = 0; g < 2; g++) {
        int nt    = g*2 + ((lane >> 4) & 1);
        int khalf = (lane >> 3) & 1;
        int row   = wn + nt*8 + (lane & 7);
        b_base[g] = (uint32_t)(16384 + row * 128 + khalf * 16);
        b_msk[g]  = (uint32_t)((row & 7) << 4);
    }

    load_chunk(A, Bm, u0, v0, 0, sb, tid);

    #pragma unroll 1
    for (int c = 0; c < NCHUNK; c++) {
        int s = c & 1;
        if (c + 1 < NCHUNK) {
            load_chunk(A, Bm, u0, v0, c + 1, sb + (s ^ 1) * STAGE_BYTES, tid);
            asm volatile("cp.async.wait_group 1;");
        } else {
            asm volatile("cp.async.wait_group 0;");
        }
        __syncthreads();

        uint32_t cbase = sb + s * STAGE_BYTES;
        #pragma unroll
        for (int ks = 0; ks < 4; ks++) {
            uint32_t a_frag[4][4], b_frag[2][4];
            #pragma unroll
            for (int mt = 0; mt < 4; mt++)
                LDMATRIX_X4(a_frag[mt], cbase + ((a_base[mt] + ks*32) ^ a_msk[mt]));
            #pragma unroll
            for (int g = 0; g < 2; g++)
                LDMATRIX_X4(b_frag[g], cbase + ((b_base[g] + ks*32) ^ b_msk[g]));
            #pragma unroll
            for (int mt = 0; mt < 4; mt++)
                #pragma unroll
                for (int nt = 0; nt < 4; nt++)
                    MMA16816(acc[mt][nt], a_frag[mt],
                             b_frag[nt >> 1][(nt & 1) * 2],
                             b_frag[nt >> 1][(nt & 1) * 2 + 1]);
        }
        __syncthreads();
    }

    float* __restrict__ Db = g_D + (size_t)b * NPIX * NPIX;
    int qrow = lane >> 2, qcol = (lane & 3) * 2;
    #pragma unroll
    for (int mt = 0; mt < 4; mt++) {
        #pragma unroll
        for (int nt = 0; nt < 4; nt++) {
            int r0  = u0 + wm + mt*16 + qrow;
            int col = v0 + wn + nt*8 + qcol;
            *(float2*)&Db[(size_t)r0       * NPIX + col] = make_float2(acc[mt][nt][0], acc[mt][nt][1]);
            *(float2*)&Db[(size_t)(r0 + 8) * NPIX + col] = make_float2(acc[mt][nt][2], acc[mt][nt][3]);
        }
    }
}

// ---------------- K3: fused diagonal-tile score + per-(q,pr) argmax ----------------
// Block = one 3-tile segment of a diagonal chain (s = qr-pr const).
// Loads nt+2 64x64 D blocks; per tile: Bsum = blk[t]+blk[t+1]+blk[t+2] (elementwise),
// scores[qc][pc] = Bsum[qc][pc] + Bsum[qc+1][pc+1] + Bsum[qc+2][pc+2].
#define SEG 3
#define AM_SBLK_OFF   0                         // 5 * 4096 floats = 81920 B
#define AM_BSUM_OFF   (5*4096*4)                // 64*66 floats = 16896 B
#define AM_RED_OFF    (AM_BSUM_OFF + 64*66*4)   // 4*64 u64 = 2048 B
#define AM_SMEM       (AM_RED_OFF + 4*64*8)     // 100864 B

__global__ void __launch_bounds__(256, 2) score_argmax_kernel()
{
    extern __shared__ char smem[];
    float* sblk = (float*)(smem + AM_SBLK_OFF);
    float* Bsum = (float*)(smem + AM_BSUM_OFF);
    unsigned long long* red2 = (unsigned long long*)(smem + AM_RED_OFF);

    int s   = (int)blockIdx.x - 61;          // diagonal id
    int j   = blockIdx.y;                    // segment along chain
    int b   = blockIdx.z;
    int len = OHW - (s < 0 ? -s : s);
    int t0  = j * SEG;
    if (t0 >= len) return;

    int qr0 = (s > 0 ? s : 0) + t0;
    int pr0 = (s < 0 ? -s : 0) + t0;
    int nt  = len - t0; if (nt > SEG) nt = SEG;
    int nb  = nt + 2;

    int tid = threadIdx.x;
    const float* __restrict__ Db = g_D + (size_t)b * NPIX * NPIX;
    uint32_t sbase = s2u(sblk);

    // load nb 64x64 blocks along D's block-diagonal
    #pragma unroll
    for (int i = 0; i < 20; i++) {
        int idx = tid + i * 256;             // 0..5119 float4 slots
        int k = idx >> 10;
        if (k < nb) {
            int w = idx & 1023;
            int row = w >> 4, c4 = (w & 15) << 2;
            const float* src = Db + (size_t)((qr0 + k) * 64 + row) * NPIX + (pr0 + k) * 64 + c4;
            uint32_t daddr = sbase + (uint32_t)(k * 4096 + row * 64 + c4) * 4;
            asm volatile("cp.async.cg.shared.global [%0], [%1], 16;" :: "r"(daddr), "l"(src));
        }
    }
    asm volatile("cp.async.commit_group;");
    asm volatile("cp.async.wait_group 0;");
    __syncthreads();

    int qc  = tid & 63;
    int pcg = tid >> 6;

    #pragma unroll 1
    for (int t = 0; t < nt; t++) {
        // stage 1: Bsum = blk[t] + blk[t+1] + blk[t+2], pitch 66
        const float* p0 = sblk + (t + 0) * 4096;
        const float* p1 = sblk + (t + 1) * 4096;
        const float* p2 = sblk + (t + 2) * 4096;
        #pragma unroll
        for (int i = 0; i < 8; i++) {
            int e2 = tid + i * 256;          // 0..2047 float2 slots
            int row = e2 >> 5, c2 = (e2 & 31) << 1;
            float2 a = *(const float2*)(p0 + row * 64 + c2);
            float2 bb = *(const float2*)(p1 + row * 64 + c2);
            float2 cc = *(const float2*)(p2 + row * 64 + c2);
            *(float2*)(Bsum + row * 66 + c2) = make_float2(a.x + bb.x + cc.x, a.y + bb.y + cc.y);
        }
        __syncthreads();

        // stage 2: 3-diagonal of Bsum + running argmax (packed, tie-break smallest p)
        unsigned long long best = 0ULL;
        if (qc < OHW) {
            const float* B0 = Bsum + qc * 66;
            const float* B1 = Bsum + (qc + 1) * 66 + 1;
            const float* B2 = Bsum + (qc + 2) * 66 + 2;
            int pgb = (pr0 + t) * OHW;
            #pragma unroll
            for (int k = 0; k < 16; k++) {
                int pc = pcg + (k << 2);
                if (pc < OHW) {
                    float sc = B0[pc] + B1[pc] + B2[pc];
                    uint32_t u = __float_as_uint(sc);
                    u ^= (u & 0x80000000u) ? 0xFFFFFFFFu : 0x80000000u;
                    unsigned long long pk =
                        ((unsigned long long)u << 32) | (uint32_t)(0xFFFFFFFFu - (pgb + pc));
                    best = umax64(best, pk);
                }
            }
        }
        red2[pcg * 64 + qc] = best;
        __syncthreads();
        if (tid < 64 && tid < OHW) {
            unsigned long long m = red2[tid];
            m = umax64(m, red2[64 + tid]);
            m = umax64(m, red2[128 + tid]);
            m = umax64(m, red2[192 + tid]);
            int bq = (b * OHW + (qr0 + t)) * OHW + tid;
            g_pack[(size_t)bq * OHW + (pr0 + t)] = m;
        }
        __syncthreads();
    }
}

// ---------------- K3b: combine per-pr partials -> g_match ----------------
__global__ void __launch_bounds__(256) combine_kernel()
{
    int bq = blockIdx.x * 8 + (threadIdx.x >> 5);
    int lane = threadIdx.x & 31;
    if (bq >= BATCH * NP) return;
    unsigned long long m = 0ULL;
    if (lane < OHW)      m = g_pack[(size_t)bq * OHW + lane];
    if (lane + 32 < OHW) m = umax64(m, g_pack[(size_t)bq * OHW + lane + 32]);
    #pragma unroll
    for (int o = 16; o > 0; o >>= 1)
        m = umax64(m, __shfl_down_sync(0xffffffffu, m, o));
    if (lane == 0)
        g_match[bq] = (int)(0xFFFFFFFFu - (uint32_t)(m & 0xFFFFFFFFu));
}

// ---------------- K4: closed-form MSE ----------------
__constant__ int c_doff[9] = {0,1,2,64,65,66,128,129,130};

__global__ void __launch_bounds__(64) loss_kernel()
{
    int b  = blockIdx.x / OHW;
    int qr = blockIdx.x - b * OHW;
    int qc = threadIdx.x;
    float val = 0.f;
    if (qc < OHW) {
        int q = qr * OHW + qc;
        int m = g_match[b * NP + q];
        int mr = m / OHW, mc = m - mr * OHW;
        int qpix = qr * HW + qc;
        int mpix = mr * HW + mc;
        const float* __restrict__ Dq = g_D + (size_t)b * NPIX * NPIX;
        int nb = b * NPIX;
        #pragma unroll
        for (int e = 0; e < 9; e++) {
            int d = c_doff[e];
            int u = qpix + d, v = mpix + d;
            float cross = g_pnorm[nb + u] * g_tnorm[nb + v] * Dq[(size_t)u * NPIX + v];
            val += g_psq[nb + u] + g_tsq[nb + v] - 2.f * cross;
        }
    }
    __shared__ float red[64];
    red[threadIdx.x] = val;
    __syncthreads();
    #pragma unroll
    for (int s = 32; s > 0; s >>= 1) {
        if (threadIdx.x < s) red[threadIdx.x] += red[threadIdx.x + s];
        __syncthreads();
    }
    if (threadIdx.x == 0) g_partial[blockIdx.x] = red[0];
}

// ---------------- K5: final reduce ----------------
__global__ void __launch_bounds__(256) finalize_kernel(float* __restrict__ out)
{
    int t = threadIdx.x;
    float v = (t < BATCH * OHW) ? g_partial[t] : 0.f;
    __shared__ float red[256];
    red[t] = v;
    __syncthreads();
    #pragma unroll
    for (int s = 128; s > 0; s >>= 1) {
        if (t < s) red[t] += red[t + s];
        __syncthreads();
    }
    if (t == 0) out[0] = red[0] * (1.f / 35426304.f);
}

// ---------------- launch ----------------
extern "C" void kernel_launch(void* const* d_in, const int* in_sizes, int n_in,
                              void* d_out, int out_size)
{
    const float* pred = (const float*)d_in[0];
    const float* targ = (const float*)d_in[1];
    float* out = (float*)d_out;

    static int smem_set = 0;
    if (!smem_set) {
        cudaFuncSetAttribute(gemm_kernel, cudaFuncAttributeMaxDynamicSharedMemorySize, GEMM_SMEM);
        cudaFuncSetAttribute(score_argmax_kernel, cudaFuncAttributeMaxDynamicSharedMemorySize, AM_SMEM);
        smem_set = 1;
    }

    normalize_kernel<<<512, 256>>>(pred, 0);
    normalize_kernel<<<512, 256>>>(targ, 1);

    dim3 ggrid(NPIX / TN, NPIX / TM, BATCH);   // 32 x 32 x 4
    gemm_kernel<<<ggrid, 256, GEMM_SMEM>>>();

    dim3 agrid(123, 21, BATCH);                // diagonals x segments x batch
    score_argmax_kernel<<<agrid, 256, AM_SMEM>>>();
    combine_kernel<<<(BATCH * NP + 7) / 8, 256>>>();

    loss_kernel<<<BATCH * OHW, 64>>>();
    finalize_kernel<<<1, 256>>>(out);
}